// round 2
// baseline (speedup 1.0000x reference)
#include <cuda_runtime.h>
#include <math.h>

#define BH_ 128
#define S_ 1024
#define D_ 64
#define TQ 64
#define TK 64
#define NTHREADS 256

// Scratch: per-(bh) sum of V rows over the masked key range [L, S)
__device__ float g_W[BH_ * D_];

// ---------------------------------------------------------------------------
// Kernel 1: W[bh][d] = sum_{k >= L_b} V[bh][k][d]
// ---------------------------------------------------------------------------
__global__ void masked_vsum_kernel(const float* __restrict__ v,
                                   const int* __restrict__ lens) {
    int bh = blockIdx.x;
    int L  = lens[bh >> 4];               // H = 16 heads share a batch's length
    int t  = threadIdx.x;                 // 256 threads
    int d  = t & 63;
    int ko = t >> 6;                      // 0..3
    const float* vb = v + (size_t)bh * S_ * D_;
    float sum = 0.f;
    for (int k = L + ko; k < S_; k += 4)
        sum += vb[k * D_ + d];
    __shared__ float red[4][D_];
    red[ko][d] = sum;
    __syncthreads();
    if (t < D_)
        g_W[bh * D_ + t] = red[0][t] + red[1][t] + red[2][t] + red[3][t];
}

// XOR swizzle on 16B granules: word index for (row, col4) in a 64x64 fp32 tile.
// Conflict-free LDS.128 for both row-strided and within-row access patterns.
__device__ __forceinline__ int swz(int row, int c4) {
    return (row << 6) + ((((c4 >> 2) ^ (row >> 2)) & 15) << 2);
}

// ---------------------------------------------------------------------------
// Kernel 2: fused masked attention, one (bh, 64-query tile) per block.
// ---------------------------------------------------------------------------
__global__ void __launch_bounds__(NTHREADS, 2)
attn_kernel(const float* __restrict__ q, const float* __restrict__ k,
            const float* __restrict__ v, const int* __restrict__ lens,
            float* __restrict__ out) {
    __shared__ float Qs[TQ * 64];     // Q tile
    __shared__ float KPs[TK * 64];    // K tile, reused as P (probabilities)
    __shared__ float Vs[TK * 64];     // V tile                (3 * 16KB = 48KB)

    int bh = blockIdx.y;
    int qt = blockIdx.x;
    int L  = lens[bh >> 4];
    int tid = threadIdx.x;
    int tr = tid >> 4, tc = tid & 15;
    int r0 = tr << 2, c0 = tc << 2;   // 4x4 microtile origin

    // ---- load Q tile (swizzled) ----
    const float* qg = q + ((size_t)bh * S_ + (size_t)qt * TQ) * D_;
    for (int i = tid; i < TQ * 16; i += NTHREADS) {
        int row = i >> 4, c4 = (i & 15) << 2;
        *(float4*)&Qs[swz(row, c4)] = *(const float4*)(qg + row * D_ + c4);
    }

    float m[4], l[4], o[4][4];
    #pragma unroll
    for (int i = 0; i < 4; i++) {
        m[i] = -INFINITY; l[i] = 0.f;
        #pragma unroll
        for (int j = 0; j < 4; j++) o[i][j] = 0.f;
    }

    int ntiles = (L + TK - 1) / TK;   // only visit tiles containing valid keys
    for (int kt = 0; kt < ntiles; kt++) {
        __syncthreads();  // previous iteration's smem reads complete
        const float* kg = k + ((size_t)bh * S_ + (size_t)kt * TK) * D_;
        const float* vg = v + ((size_t)bh * S_ + (size_t)kt * TK) * D_;
        for (int i = tid; i < TK * 16; i += NTHREADS) {
            int row = i >> 4, c4 = (i & 15) << 2;
            *(float4*)&KPs[swz(row, c4)] = *(const float4*)(kg + row * D_ + c4);
            *(float4*)&Vs[swz(row, c4)]  = *(const float4*)(vg + row * D_ + c4);
        }
        __syncthreads();

        // ---- S = Q K^T (64x64x64), each thread a 4x4 microtile ----
        float s[4][4];
        #pragma unroll
        for (int i = 0; i < 4; i++)
            #pragma unroll
            for (int j = 0; j < 4; j++) s[i][j] = 0.f;

        #pragma unroll 4
        for (int kk = 0; kk < 64; kk += 4) {
            float4 a[4], b[4];
            #pragma unroll
            for (int i = 0; i < 4; i++) a[i] = *(const float4*)&Qs[swz(r0 + i, kk)];
            #pragma unroll
            for (int j = 0; j < 4; j++) b[j] = *(const float4*)&KPs[swz(c0 + j, kk)];
            #pragma unroll
            for (int i = 0; i < 4; i++)
                #pragma unroll
                for (int j = 0; j < 4; j++)
                    s[i][j] += a[i].x * b[j].x + a[i].y * b[j].y
                             + a[i].z * b[j].z + a[i].w * b[j].w;
        }

        // ---- scale, mask (exclude k>=L; merged exactly via the lump), online softmax ----
        int kbase = kt * TK + c0;
        float alpha[4];
        #pragma unroll
        for (int i = 0; i < 4; i++) {
            #pragma unroll
            for (int j = 0; j < 4; j++) {
                float sv = s[i][j] * 0.125f;              // 1/sqrt(64)
                if (kbase + j >= L) sv = -INFINITY;       // excluded here, merged later
                s[i][j] = sv;
            }
            float mx = fmaxf(fmaxf(s[i][0], s[i][1]), fmaxf(s[i][2], s[i][3]));
            #pragma unroll
            for (int off = 8; off; off >>= 1)
                mx = fmaxf(mx, __shfl_xor_sync(0xffffffffu, mx, off));
            float mn = fmaxf(m[i], mx);
            alpha[i] = __expf(m[i] - mn);
            m[i] = mn;
            float rs = 0.f;
            #pragma unroll
            for (int j = 0; j < 4; j++) {
                float p = __expf(s[i][j] - mn);
                s[i][j] = p;
                rs += p;
            }
            #pragma unroll
            for (int off = 8; off; off >>= 1)
                rs += __shfl_xor_sync(0xffffffffu, rs, off);
            l[i] = l[i] * alpha[i] + rs;
        }

        // ---- write P into the K buffer ----
        __syncthreads();
        #pragma unroll
        for (int i = 0; i < 4; i++)
            *(float4*)&KPs[swz(r0 + i, c0)] =
                make_float4(s[i][0], s[i][1], s[i][2], s[i][3]);
        __syncthreads();

        // ---- rescale accumulator, O += P V (64x64x64) ----
        #pragma unroll
        for (int i = 0; i < 4; i++)
            #pragma unroll
            for (int j = 0; j < 4; j++) o[i][j] *= alpha[i];

        #pragma unroll 4
        for (int kk = 0; kk < 64; kk += 4) {
            float4 a[4];
            #pragma unroll
            for (int i = 0; i < 4; i++) a[i] = *(const float4*)&KPs[swz(r0 + i, kk)];
            float4 vv[4];
            #pragma unroll
            for (int jj = 0; jj < 4; jj++) vv[jj] = *(const float4*)&Vs[swz(kk + jj, c0)];
            #pragma unroll
            for (int i = 0; i < 4; i++) {
                float av0 = a[i].x, av1 = a[i].y, av2 = a[i].z, av3 = a[i].w;
                o[i][0] += av0 * vv[0].x + av1 * vv[1].x + av2 * vv[2].x + av3 * vv[3].x;
                o[i][1] += av0 * vv[0].y + av1 * vv[1].y + av2 * vv[2].y + av3 * vv[3].y;
                o[i][2] += av0 * vv[0].z + av1 * vv[1].z + av2 * vv[2].z + av3 * vv[3].z;
                o[i][3] += av0 * vv[0].w + av1 * vv[1].w + av2 * vv[2].w + av3 * vv[3].w;
            }
        }
    }

    // ---- merge the masked lump: (S-L) keys each at score 1e-6, V-sum = W ----
    if (L < S_) {
        float4 Wv = *(const float4*)&g_W[bh * D_ + c0];
        float mcnt = (float)(S_ - L);
        #pragma unroll
        for (int i = 0; i < 4; i++) {
            float mn = fmaxf(m[i], 1e-6f);
            float al = __expf(m[i] - mn);
            float pm = __expf(1e-6f - mn);
            l[i] = l[i] * al + mcnt * pm;
            o[i][0] = o[i][0] * al + pm * Wv.x;
            o[i][1] = o[i][1] * al + pm * Wv.y;
            o[i][2] = o[i][2] * al + pm * Wv.z;
            o[i][3] = o[i][3] * al + pm * Wv.w;
        }
    }

    // ---- normalize and store ----
    float* og = out + ((size_t)bh * S_ + (size_t)qt * TQ) * D_;
    #pragma unroll
    for (int i = 0; i < 4; i++) {
        float inv = 1.f / l[i];
        *(float4*)(og + (r0 + i) * D_ + c0) =
            make_float4(o[i][0] * inv, o[i][1] * inv, o[i][2] * inv, o[i][3] * inv);
    }
}

extern "C" void kernel_launch(void* const* d_in, const int* in_sizes, int n_in,
                              void* d_out, int out_size) {
    const float* q    = (const float*)d_in[0];
    const float* k    = (const float*)d_in[1];
    const float* v    = (const float*)d_in[2];
    const int*   lens = (const int*)d_in[3];    // JAX x64 disabled -> int32 on device
    float*       out  = (float*)d_out;

    masked_vsum_kernel<<<BH_, NTHREADS>>>(v, lens);
    dim3 grid(S_ / TQ, BH_);
    attn_kernel<<<grid, NTHREADS>>>(q, k, v, lens, out);
}

// round 3
// speedup vs baseline: 1.0476x; 1.0476x over previous
#include <cuda_runtime.h>
#include <math.h>

#define BH_ 128
#define S_ 1024
#define D_ 64
#define TQ 64
#define TK 64
#define NTHREADS 256

// Scratch: per-(bh) sum of V rows over the masked key range [L, S)
__device__ float g_W[BH_ * D_];

// ---------------------------------------------------------------------------
// Kernel 1: W[bh][d] = sum_{k >= L_b} V[bh][k][d]
// ---------------------------------------------------------------------------
__global__ void masked_vsum_kernel(const float* __restrict__ v,
                                   const int* __restrict__ lens) {
    int bh = blockIdx.x;
    int L  = lens[bh >> 4];               // H = 16 heads share a batch's length
    int t  = threadIdx.x;                 // 256 threads
    int d  = t & 63;
    int ko = t >> 6;                      // 0..3
    const float* vb = v + (size_t)bh * S_ * D_;
    float sum = 0.f;
    for (int k = L + ko; k < S_; k += 4)
        sum += vb[k * D_ + d];
    __shared__ float red[4][D_];
    red[ko][d] = sum;
    __syncthreads();
    if (t < D_)
        g_W[bh * D_ + t] = red[0][t] + red[1][t] + red[2][t] + red[3][t];
}

// XOR swizzle on 16B granules: word index for (row, col4) in a 64x64 fp32 tile.
// Conflict-free LDS.128 for both row-strided and within-row access patterns.
__device__ __forceinline__ int swz(int row, int c4) {
    return (row << 6) + ((((c4 >> 2) ^ (row >> 2)) & 15) << 2);
}

// ---------------------------------------------------------------------------
// Kernel 2: fused masked attention, one (bh, 64-query tile) per block.
// ---------------------------------------------------------------------------
__global__ void __launch_bounds__(NTHREADS, 2)
attn_kernel(const float* __restrict__ q, const float* __restrict__ k,
            const float* __restrict__ v, const int* __restrict__ lens,
            float* __restrict__ out) {
    __shared__ float Qs[TQ * 64];     // Q tile
    __shared__ float KPs[TK * 64];    // K tile, reused as P (probabilities)
    __shared__ float Vs[TK * 64];     // V tile                (3 * 16KB = 48KB)

    int bh = blockIdx.y;
    int qt = blockIdx.x;
    int L  = lens[bh >> 4];
    int tid = threadIdx.x;
    int tr = tid >> 4, tc = tid & 15;
    int r0 = tr << 2, c0 = tc << 2;   // 4x4 microtile origin

    // ---- load Q tile (swizzled) ----
    const float* qg = q + ((size_t)bh * S_ + (size_t)qt * TQ) * D_;
    for (int i = tid; i < TQ * 16; i += NTHREADS) {
        int row = i >> 4, c4 = (i & 15) << 2;
        *(float4*)&Qs[swz(row, c4)] = *(const float4*)(qg + row * D_ + c4);
    }

    float m[4], l[4], o[4][4];
    #pragma unroll
    for (int i = 0; i < 4; i++) {
        m[i] = -INFINITY; l[i] = 0.f;
        #pragma unroll
        for (int j = 0; j < 4; j++) o[i][j] = 0.f;
    }

    int ntiles = (L + TK - 1) / TK;   // only visit tiles containing valid keys
    for (int kt = 0; kt < ntiles; kt++) {
        __syncthreads();  // previous iteration's smem reads complete
        const float* kg = k + ((size_t)bh * S_ + (size_t)kt * TK) * D_;
        const float* vg = v + ((size_t)bh * S_ + (size_t)kt * TK) * D_;
        for (int i = tid; i < TK * 16; i += NTHREADS) {
            int row = i >> 4, c4 = (i & 15) << 2;
            *(float4*)&KPs[swz(row, c4)] = *(const float4*)(kg + row * D_ + c4);
            *(float4*)&Vs[swz(row, c4)]  = *(const float4*)(vg + row * D_ + c4);
        }
        __syncthreads();

        // ---- S = Q K^T (64x64x64), each thread a 4x4 microtile ----
        float s[4][4];
        #pragma unroll
        for (int i = 0; i < 4; i++)
            #pragma unroll
            for (int j = 0; j < 4; j++) s[i][j] = 0.f;

        #pragma unroll 4
        for (int kk = 0; kk < 64; kk += 4) {
            float4 a[4], b[4];
            #pragma unroll
            for (int i = 0; i < 4; i++) a[i] = *(const float4*)&Qs[swz(r0 + i, kk)];
            #pragma unroll
            for (int j = 0; j < 4; j++) b[j] = *(const float4*)&KPs[swz(c0 + j, kk)];
            #pragma unroll
            for (int i = 0; i < 4; i++)
                #pragma unroll
                for (int j = 0; j < 4; j++)
                    s[i][j] += a[i].x * b[j].x + a[i].y * b[j].y
                             + a[i].z * b[j].z + a[i].w * b[j].w;
        }

        // ---- scale, mask (exclude k>=L; merged exactly via the lump), online softmax ----
        int kbase = kt * TK + c0;
        float alpha[4];
        #pragma unroll
        for (int i = 0; i < 4; i++) {
            #pragma unroll
            for (int j = 0; j < 4; j++) {
                float sv = s[i][j] * 0.125f;              // 1/sqrt(64)
                if (kbase + j >= L) sv = -INFINITY;       // excluded here, merged later
                s[i][j] = sv;
            }
            float mx = fmaxf(fmaxf(s[i][0], s[i][1]), fmaxf(s[i][2], s[i][3]));
            #pragma unroll
            for (int off = 8; off; off >>= 1)
                mx = fmaxf(mx, __shfl_xor_sync(0xffffffffu, mx, off));
            float mn = fmaxf(m[i], mx);
            alpha[i] = __expf(m[i] - mn);
            m[i] = mn;
            float rs = 0.f;
            #pragma unroll
            for (int j = 0; j < 4; j++) {
                float p = __expf(s[i][j] - mn);
                s[i][j] = p;
                rs += p;
            }
            #pragma unroll
            for (int off = 8; off; off >>= 1)
                rs += __shfl_xor_sync(0xffffffffu, rs, off);
            l[i] = l[i] * alpha[i] + rs;
        }

        // ---- write P into the K buffer ----
        __syncthreads();
        #pragma unroll
        for (int i = 0; i < 4; i++)
            *(float4*)&KPs[swz(r0 + i, c0)] =
                make_float4(s[i][0], s[i][1], s[i][2], s[i][3]);
        __syncthreads();

        // ---- rescale accumulator, O += P V (64x64x64) ----
        #pragma unroll
        for (int i = 0; i < 4; i++)
            #pragma unroll
            for (int j = 0; j < 4; j++) o[i][j] *= alpha[i];

        #pragma unroll 4
        for (int kk = 0; kk < 64; kk += 4) {
            float4 a[4];
            #pragma unroll
            for (int i = 0; i < 4; i++) a[i] = *(const float4*)&KPs[swz(r0 + i, kk)];
            float4 vv[4];
            #pragma unroll
            for (int jj = 0; jj < 4; jj++) vv[jj] = *(const float4*)&Vs[swz(kk + jj, c0)];
            #pragma unroll
            for (int i = 0; i < 4; i++) {
                float av0 = a[i].x, av1 = a[i].y, av2 = a[i].z, av3 = a[i].w;
                o[i][0] += av0 * vv[0].x + av1 * vv[1].x + av2 * vv[2].x + av3 * vv[3].x;
                o[i][1] += av0 * vv[0].y + av1 * vv[1].y + av2 * vv[2].y + av3 * vv[3].y;
                o[i][2] += av0 * vv[0].z + av1 * vv[1].z + av2 * vv[2].z + av3 * vv[3].z;
                o[i][3] += av0 * vv[0].w + av1 * vv[1].w + av2 * vv[2].w + av3 * vv[3].w;
            }
        }
    }

    // ---- merge the masked lump: (S-L) keys each at score 1e-6, V-sum = W ----
    if (L < S_) {
        float4 Wv = *(const float4*)&g_W[bh * D_ + c0];
        float mcnt = (float)(S_ - L);
        #pragma unroll
        for (int i = 0; i < 4; i++) {
            float mn = fmaxf(m[i], 1e-6f);
            float al = __expf(m[i] - mn);
            float pm = __expf(1e-6f - mn);
            l[i] = l[i] * al + mcnt * pm;
            o[i][0] = o[i][0] * al + pm * Wv.x;
            o[i][1] = o[i][1] * al + pm * Wv.y;
            o[i][2] = o[i][2] * al + pm * Wv.z;
            o[i][3] = o[i][3] * al + pm * Wv.w;
        }
    }

    // ---- normalize and store ----
    float* og = out + ((size_t)bh * S_ + (size_t)qt * TQ) * D_;
    #pragma unroll
    for (int i = 0; i < 4; i++) {
        float inv = 1.f / l[i];
        *(float4*)(og + (r0 + i) * D_ + c0) =
            make_float4(o[i][0] * inv, o[i][1] * inv, o[i][2] * inv, o[i][3] * inv);
    }
}

extern "C" void kernel_launch(void* const* d_in, const int* in_sizes, int n_in,
                              void* d_out, int out_size) {
    const float* q    = (const float*)d_in[0];
    const float* k    = (const float*)d_in[1];
    const float* v    = (const float*)d_in[2];
    const int*   lens = (const int*)d_in[3];    // JAX x64 disabled -> int32 on device
    float*       out  = (float*)d_out;

    masked_vsum_kernel<<<BH_, NTHREADS>>>(v, lens);
    dim3 grid(S_ / TQ, BH_);
    attn_kernel<<<grid, NTHREADS>>>(q, k, v, lens, out);
}